// round 6
// baseline (speedup 1.0000x reference)
#include <cuda_runtime.h>
#include <cuda_fp16.h>

#define HID 5
#define HDIM 2048
#define BSZ 16384
#define NU 3          // units per lane (lane1's 3rd is a zero dummy)

__device__ int g_lengths[BSZ];

// ---------------------------------------------------------------------------
// Kernel 1: per-row nonzero count (ragged length, matches reference mask)
// ---------------------------------------------------------------------------
__global__ void len_kernel(const float* __restrict__ x) {
    int b = blockIdx.x;
    const float4* row = reinterpret_cast<const float4*>(x + (size_t)b * HDIM);
    int tid = threadIdx.x;
    int cnt = 0;
#pragma unroll
    for (int i = 0; i < 2; i++) {
        float4 v = row[tid + i * 256];
        cnt += (v.x != 0.f) + (v.y != 0.f) + (v.z != 0.f) + (v.w != 0.f);
    }
    __shared__ int s[8];
#pragma unroll
    for (int o = 16; o > 0; o >>= 1) cnt += __shfl_down_sync(0xffffffffu, cnt, o);
    if ((tid & 31) == 0) s[tid >> 5] = cnt;
    __syncthreads();
    if (tid < 8) {
        int v = s[tid];
#pragma unroll
        for (int o = 4; o > 0; o >>= 1) v += __shfl_down_sync(0xffu, v, o);
        if (tid == 0) g_lengths[b] = v;
    }
}

// ---------------------------------------------------------------------------
// math helpers
// ---------------------------------------------------------------------------
__device__ __forceinline__ float fast_tanh(float v) {
    float r; asm("tanh.approx.f32 %0, %1;" : "=f"(r) : "f"(v)); return r;
}
__device__ __forceinline__ unsigned tanh2u(unsigned u) {
    unsigned r; asm("tanh.approx.f16x2 %0, %1;" : "=r"(r) : "r"(u)); return r;
}
__device__ __forceinline__ unsigned pack_h2(float lo, float hi) {
    unsigned r; asm("cvt.rn.f16x2.f32 %0, %1, %2;" : "=r"(r) : "f"(hi), "f"(lo));
    return r;
}
__device__ __forceinline__ __half2 u2h(unsigned u) { return *reinterpret_cast<__half2*>(&u); }
__device__ __forceinline__ unsigned h2u(__half2 h) { return *reinterpret_cast<unsigned*>(&h); }
__device__ __forceinline__ unsigned dup_lo(unsigned v) { return __byte_perm(v, v, 0x1010); }
__device__ __forceinline__ unsigned dup_hi(unsigned v) { return __byte_perm(v, v, 0x3232); }

// ---------------------------------------------------------------------------
// LSTM: 2 threads per sequence (lane pair). Lane p=0 -> units 0..2,
// lane p=1 -> units 3,4 (+ zero dummy). Gate pairs per unit:
//   P = {0.5*i, 0.5*f},  Q = {0.5*o, g}.  sig(x)=0.5*tanh(0.5x)+0.5.
// h exchanged pairwise via shfl.xor; weight columns reordered so each lane
// accumulates its LOCAL h terms first (hides shuffle latency).
// ---------------------------------------------------------------------------
struct PairState {
    float c[NU], h[NU];
    unsigned ownA, ownB;   // packed {h_loc0,h_loc1}, {h_loc2, 0}
    unsigned rcvA, rcvB;   // peer's packed h from last shuffle
};

__device__ __forceinline__ void lstm_step(
    PairState& st, float xv, int p, unsigned pmask,
    const __half2* __restrict__ wih, const __half2* __restrict__ bs,
    const __half2 (*whh)[HID])
{
    // broadcast pairs bb[j] = {h_ord[j], h_ord[j]}; local h first (j=0,1[,2])
    __half2 bb[HID];
    bb[0] = u2h(dup_lo(st.ownA));
    bb[1] = u2h(dup_hi(st.ownA));
    bb[2] = u2h(p ? dup_lo(st.rcvA) : dup_lo(st.ownB));
    bb[3] = u2h(p ? dup_hi(st.rcvA) : dup_lo(st.rcvA));
    bb[4] = u2h(p ? dup_lo(st.rcvB) : dup_hi(st.rcvA));

    const __half2 x2 = __float2half2_rn(xv);
    __half2 a[2 * NU];
#pragma unroll
    for (int q = 0; q < 2 * NU; q++) a[q] = __hfma2(x2, wih[q], bs[q]);
#pragma unroll
    for (int j = 0; j < HID; j++)
#pragma unroll
        for (int q = 0; q < 2 * NU; q++) a[q] = __hfma2(bb[j], whh[q][j], a[q]);

    const __half2 h05 = __float2half2_rn(0.5f);
#pragma unroll
    for (int k = 0; k < NU; k++) {
        const __half2 sP = __hfma2(u2h(tanh2u(h2u(a[2 * k]))), h05, h05); // {ig,fg}
        const __half2 tQ = u2h(tanh2u(h2u(a[2 * k + 1])));                // {t(.5o), -}
        const float ig = __low2float(sP);
        const float fg = __high2float(sP);
        const float og = fmaf(__low2float(tQ), 0.5f, 0.5f);
        const float tg = fast_tanh(__high2float(a[2 * k + 1]));          // fp32 tanh(g)
        const float cn = fmaf(fg, st.c[k], ig * tg);
        st.c[k] = cn;
        st.h[k] = og * fast_tanh(cn);
    }
    st.ownA = pack_h2(st.h[0], st.h[1]);
    st.ownB = pack_h2(st.h[2], 0.f);
    st.rcvA = __shfl_xor_sync(pmask, st.ownA, 1);
    st.rcvB = __shfl_xor_sync(pmask, st.ownB, 1);
}

__global__ void __launch_bounds__(64, 1) lstm_kernel(
    const float* __restrict__ x,
    const float* __restrict__ W_ih,
    const float* __restrict__ W_hh,
    const float* __restrict__ b_ih,
    const float* __restrict__ b_hh,
    float* __restrict__ out)
{
    const int tid = blockIdx.x * blockDim.x + threadIdx.x;
    const int b = tid >> 1;
    const int p = tid & 1;
    const unsigned pmask = 3u << (threadIdx.x & 30);

    // column order: local h first. lane0: [0,1,2,3,4]; lane1: [3,4,0,1,2]
    int ord[HID];
#pragma unroll
    for (int j = 0; j < HID; j++) ord[j] = p ? ((j < 2) ? 3 + j : j - 2) : j;

    __half2 wih[2 * NU], bs[2 * NU], whh[2 * NU][HID];
#pragma unroll
    for (int k = 0; k < NU; k++) {
        const int u = p * NU + k;
        const bool dm = (u >= HID);            // dummy unit (lane1, k==2)
        const int ri = dm ? 0 : u, rf = dm ? 0 : HID + u,
                  rg = dm ? 0 : 2 * HID + u, ro = dm ? 0 : 3 * HID + u;
        const float z = dm ? 0.f : 1.f;
        wih[2 * k]     = __floats2half2_rn(z * 0.5f * W_ih[ri], z * 0.5f * W_ih[rf]);
        wih[2 * k + 1] = __floats2half2_rn(z * 0.5f * W_ih[ro], z * W_ih[rg]);
        bs[2 * k]      = __floats2half2_rn(z * 0.5f * (b_ih[ri] + b_hh[ri]),
                                           z * 0.5f * (b_ih[rf] + b_hh[rf]));
        bs[2 * k + 1]  = __floats2half2_rn(z * 0.5f * (b_ih[ro] + b_hh[ro]),
                                           z * (b_ih[rg] + b_hh[rg]));
#pragma unroll
        for (int j = 0; j < HID; j++) {
            const int c = ord[j];
            whh[2 * k][j]     = __floats2half2_rn(z * 0.5f * W_hh[ri * HID + c],
                                                  z * 0.5f * W_hh[rf * HID + c]);
            whh[2 * k + 1][j] = __floats2half2_rn(z * 0.5f * W_hh[ro * HID + c],
                                                  z * W_hh[rg * HID + c]);
        }
    }

    const int len = g_lengths[b];
    const float* row = x + (size_t)b * HDIM;

    PairState st;
#pragma unroll
    for (int k = 0; k < NU; k++) { st.c[k] = 0.f; st.h[k] = 0.f; }
    st.ownA = st.ownB = st.rcvA = st.rcvB = 0u;

    float4 a0 = make_float4(0.f, 0.f, 0.f, 0.f);
    if (len > 0) a0 = *reinterpret_cast<const float4*>(row);

    for (int t0 = 0; t0 < len; t0 += 4) {
        float4 nx = a0;
        const int nt = t0 + 4;
        if (nt < HDIM) nx = *reinterpret_cast<const float4*>(row + nt);

        const int nrem = len - t0;
        if (nrem >= 4) {
            lstm_step(st, a0.x, p, pmask, wih, bs, whh);
            lstm_step(st, a0.y, p, pmask, wih, bs, whh);
            lstm_step(st, a0.z, p, pmask, wih, bs, whh);
            lstm_step(st, a0.w, p, pmask, wih, bs, whh);
        } else {
            float xs[4] = {a0.x, a0.y, a0.z, a0.w};
#pragma unroll
            for (int k = 0; k < 4; k++)
                if (k < nrem)
                    lstm_step(st, xs[k], p, pmask, wih, bs, whh);
        }
        a0 = nx;
    }

#pragma unroll
    for (int k = 0; k < NU; k++) {
        const int u = p * NU + k;
        if (u < HID) out[b * HID + u] = st.h[k];
    }
}

// ---------------------------------------------------------------------------
extern "C" void kernel_launch(void* const* d_in, const int* in_sizes, int n_in,
                              void* d_out, int out_size) {
    const float* x    = (const float*)d_in[0];
    const float* W_ih = (const float*)d_in[1];
    const float* W_hh = (const float*)d_in[2];
    const float* b_ih = (const float*)d_in[3];
    const float* b_hh = (const float*)d_in[4];
    float* out = (float*)d_out;

    len_kernel<<<BSZ, 256>>>(x);
    lstm_kernel<<<(BSZ * 2) / 64, 64>>>(x, W_ih, W_hh, b_ih, b_hh, out);
}